// round 4
// baseline (speedup 1.0000x reference)
#include <cuda_runtime.h>
#include <cstdint>

#define LAYERS 8
#define EPS_F 1e-7f

typedef unsigned long long ull;

__device__ __forceinline__ ull pack2(float x, float y) {
    ull r; asm("mov.b64 %0, {%1, %2};" : "=l"(r) : "f"(x), "f"(y)); return r;
}
__device__ __forceinline__ void unpack2(ull v, float& x, float& y) {
    asm("mov.b64 {%0, %1}, %2;" : "=f"(x), "=f"(y) : "l"(v));
}
__device__ __forceinline__ ull fma2(ull a, ull b, ull c) {
    ull d; asm("fma.rn.f32x2 %0, %1, %2, %3;" : "=l"(d) : "l"(a), "l"(b), "l"(c)); return d;
}
__device__ __forceinline__ ull mul2(ull a, ull b) {
    ull d; asm("mul.rn.f32x2 %0, %1, %2;" : "=l"(d) : "l"(a), "l"(b)); return d;
}
__device__ __forceinline__ ull add2(ull a, ull b) {
    ull d; asm("add.rn.f32x2 %0, %1, %2;" : "=l"(d) : "l"(a), "l"(b)); return d;
}

// ---------------------------------------------------------------------------
// Fused kernel. Per-block cooperative precompute of the 3 folded circuit
// matrices (column phases {1,-i,-i,-1} folded in). Matrix stored in smem as
// DUPLICATED packed words (Mre,Mre) / (Mim,Mim) so a single f32x2 FMA chain
// evaluates one row for TWO batch elements at once.
// out layout: [pi (B,3) | mu (B,3) | sigma (B,3)], row-major.
// ---------------------------------------------------------------------------
__global__ void __launch_bounds__(256, 4)
qmdn_fused(const float4* __restrict__ x4,
           const float* __restrict__ wp,
           const float* __restrict__ wm,
           const float* __restrict__ ws,
           float* __restrict__ out, int B) {
    __shared__ float sR[3][LAYERS][2][2][2][2];   // q, layer, wire, row, col, re/im
    __shared__ float sP[3][LAYERS][4][4][2];      // workspace for layer products
    __shared__ ull   sMre[3][16];                 // (Mre, Mre) packed dup
    __shared__ ull   sMim[3][16];                 // (Mim, Mim) packed dup

    int tid  = threadIdx.x;
    int wid  = tid >> 5;
    int lane = tid & 31;

    if (wid < 3) {
        int q = wid;
        const float* w = (q == 0) ? wp : (q == 1) ? wm : ws;

        // 1. all 16 Rot gates in parallel (lane = 2*layer + wire)
        if (lane < 16) {
            int l = lane >> 1, wi = lane & 1;
            float phi = w[(l * 2 + wi) * 3 + 0];
            float th  = w[(l * 2 + wi) * 3 + 1];
            float om  = w[(l * 2 + wi) * 3 + 2];
            float st, ct, sapo, capo, samo, camo;
            __sincosf(0.5f * th, &st, &ct);
            __sincosf(0.5f * (phi + om), &sapo, &capo);
            __sincosf(0.5f * (phi - om), &samo, &camo);
            sR[q][l][wi][0][0][0] =  capo * ct;  sR[q][l][wi][0][0][1] = -sapo * ct;
            sR[q][l][wi][0][1][0] = -camo * st;  sR[q][l][wi][0][1][1] = -samo * st;
            sR[q][l][wi][1][0][0] =  camo * st;  sR[q][l][wi][1][0][1] = -samo * st;
            sR[q][l][wi][1][1][0] =  capo * ct;  sR[q][l][wi][1][1][1] =  sapo * ct;
        }
        __syncwarp();

        // 2. per-layer PK = row-permuted Kronecker (lane = 4*r + c)
        if (lane < 16) {
            int r = lane >> 2, c = lane & 3;
            const int src[4] = {0, 2, 3, 1};
            int rs = src[r], i0 = rs >> 1, j0 = rs & 1, i1 = c >> 1, j1 = c & 1;
#pragma unroll
            for (int l = 0; l < LAYERS; l++) {
                float ar = sR[q][l][0][i0][i1][0], ai = sR[q][l][0][i0][i1][1];
                float br = sR[q][l][1][j0][j1][0], bi = sR[q][l][1][j0][j1][1];
                sP[q][l][r][c][0] = ar * br - ai * bi;
                sP[q][l][r][c][1] = ar * bi + ai * br;
            }
        }
        __syncwarp();

        // 3. log-tree product: U = PK7 * PK6 * ... * PK0
        for (int np = 4; np >= 1; np >>= 1) {
            float res[4][2];
            if (lane < 16) {
                int r = lane >> 2, c = lane & 3;
                for (int m = 0; m < np; m++) {
                    float sr = 0.f, si = 0.f;
#pragma unroll
                    for (int k = 0; k < 4; k++) {
                        float ar = sP[q][2 * m + 1][r][k][0], ai = sP[q][2 * m + 1][r][k][1];
                        float br = sP[q][2 * m][k][c][0],     bi = sP[q][2 * m][k][c][1];
                        sr += ar * br - ai * bi;
                        si += ar * bi + ai * br;
                    }
                    res[m][0] = sr; res[m][1] = si;
                }
            }
            __syncwarp();
            if (lane < 16) {
                int r = lane >> 2, c = lane & 3;
                for (int m = 0; m < np; m++) {
                    sP[q][m][r][c][0] = res[m][0];
                    sP[q][m][r][c][1] = res[m][1];
                }
            }
            __syncwarp();
        }

        // 4. fold column phases {1, -i, -i, -1}, store duplicated packs
        if (lane < 16) {
            int r = lane >> 2, c = lane & 3;
            float ur = sP[q][0][r][c][0], ui = sP[q][0][r][c][1];
            float mr, mi;
            if (c == 0)      { mr =  ur; mi =  ui; }
            else if (c == 3) { mr = -ur; mi = -ui; }
            else             { mr =  ui; mi = -ur; }   // -i*(a+bi) = b - a i
            sMre[q][r * 4 + c] = pack2(mr, mr);
            sMim[q][r * 4 + c] = pack2(mi, mi);
        }
    }
    __syncthreads();

    // ------------------- main loop: 4 elems/thread, pair-packed -------------------
    int nGroups = B >> 2;
    int stride  = gridDim.x * blockDim.x;
    const float CLIP_LO = EPS_F;
    const float CLIP_HI = 1.0f - EPS_F;
    const float LN2 = 0.69314718056f;
    size_t regionStride = 3 * (size_t)B;

    for (int t = blockIdx.x * blockDim.x + tid; t < nGroups; t += stride) {
        float4 xv = x4[t];
        float xs[4] = {xv.x, xv.y, xv.z, xv.w};

        // amplitudes packed by element-pair: pp[h][k] = (a[2h][k], a[2h+1][k])
        ull pp[2][4];
#pragma unroll
        for (int h = 0; h < 2; h++) {
            float s0a, c0a, s1a, c1a, s0b, c0b, s1b, c1b;
            __sincosf(0.5f * xs[2 * h], &s0a, &c0a);
            __sincosf(0.78539816339744831f * xs[2 * h], &s1a, &c1a);
            __sincosf(0.5f * xs[2 * h + 1], &s0b, &c0b);
            __sincosf(0.78539816339744831f * xs[2 * h + 1], &s1b, &c1b);
            pp[h][0] = pack2(c0a * c1a, c0b * c1b);
            pp[h][1] = pack2(c0a * s1a, c0b * s1b);
            pp[h][2] = pack2(s0a * c1a, s0b * c1b);
            pp[h][3] = pack2(s0a * s1a, s0b * s1b);
        }

#pragma unroll
        for (int q = 0; q < 3; q++) {
            int nrows = (q == 0) ? 3 : 4;
            float p[2][4][2];    // [pair][row][elem-in-pair] -> scalar probs
#pragma unroll
            for (int j = 0; j < 4; j++) {
                if (j >= nrows) break;
                ull mr0 = sMre[q][j * 4 + 0], mr1 = sMre[q][j * 4 + 1];
                ull mr2 = sMre[q][j * 4 + 2], mr3 = sMre[q][j * 4 + 3];
                ull mi0 = sMim[q][j * 4 + 0], mi1 = sMim[q][j * 4 + 1];
                ull mi2 = sMim[q][j * 4 + 2], mi3 = sMim[q][j * 4 + 3];
#pragma unroll
                for (int h = 0; h < 2; h++) {
                    ull re2 = mul2(mr0, pp[h][0]);
                    re2 = fma2(mr1, pp[h][1], re2);
                    re2 = fma2(mr2, pp[h][2], re2);
                    re2 = fma2(mr3, pp[h][3], re2);
                    ull im2 = mul2(mi0, pp[h][0]);
                    im2 = fma2(mi1, pp[h][1], im2);
                    im2 = fma2(mi2, pp[h][2], im2);
                    im2 = fma2(mi3, pp[h][3], im2);
                    ull p2 = add2(mul2(re2, re2), mul2(im2, im2));
                    unpack2(p2, p[h][j][0], p[h][j][1]);
                }
            }

            float o[12];
#pragma unroll
            for (int h = 0; h < 2; h++) {
#pragma unroll
                for (int s = 0; s < 2; s++) {
                    int e = 2 * h + s;
                    if (q == 0) {
                        float inv = __fdividef(1.0f, p[h][0][s] + p[h][1][s] + p[h][2][s]);
                        o[e * 3 + 0] = p[h][0][s] * inv;
                        o[e * 3 + 1] = p[h][1][s] * inv;
                        o[e * 3 + 2] = p[h][2][s] * inv;
                    } else {
                        float pc[4];
#pragma unroll
                        for (int j = 0; j < 4; j++)
                            pc[j] = fminf(fmaxf(p[h][j][s], CLIP_LO), CLIP_HI);
                        if (q == 1) {
                            float l3 = __log2f(pc[3]);
                            o[e * 3 + 0] = (__log2f(pc[0]) - l3) * LN2;
                            o[e * 3 + 1] = (__log2f(pc[1]) - l3) * LN2;
                            o[e * 3 + 2] = (__log2f(pc[2]) - l3) * LN2;
                        } else {
                            float inv = __fdividef(1.0f, pc[3]);
                            o[e * 3 + 0] = pc[0] * inv;
                            o[e * 3 + 1] = pc[1] * inv;
                            o[e * 3 + 2] = pc[2] * inv;
                        }
                    }
                }
            }
            float4* dst = (float4*)(out + q * regionStride + (size_t)t * 12);
            dst[0] = make_float4(o[0], o[1], o[2],  o[3]);
            dst[1] = make_float4(o[4], o[5], o[6],  o[7]);
            dst[2] = make_float4(o[8], o[9], o[10], o[11]);
        }
    }
}

extern "C" void kernel_launch(void* const* d_in, const int* in_sizes, int n_in,
                              void* d_out, int out_size) {
    const float* x  = (const float*)d_in[0];
    const float* wp = (const float*)d_in[1];
    const float* wm = (const float*)d_in[2];
    const float* ws = (const float*)d_in[3];
    float* out = (float*)d_out;
    int B = in_sizes[0];

    int nGroups = B >> 2;
    int threads = 256;
    int blocks = (nGroups + threads - 1) / threads;   // 1024 @ B=2^20, 1 group/thread
    qmdn_fused<<<blocks, threads>>>((const float4*)x, wp, wm, ws, out, B);
}

// round 5
// speedup vs baseline: 1.0418x; 1.0418x over previous
#include <cuda_runtime.h>
#include <cstdint>

#define LAYERS 8
#define EPS_F 1e-7f

typedef unsigned long long ull;

__device__ __forceinline__ ull pack2(float x, float y) {
    ull r; asm("mov.b64 %0, {%1, %2};" : "=l"(r) : "f"(x), "f"(y)); return r;
}
__device__ __forceinline__ void unpack2(ull v, float& x, float& y) {
    asm("mov.b64 {%0, %1}, %2;" : "=f"(x), "=f"(y) : "l"(v));
}
__device__ __forceinline__ ull fma2(ull a, ull b, ull c) {
    ull d; asm("fma.rn.f32x2 %0, %1, %2, %3;" : "=l"(d) : "l"(a), "l"(b), "l"(c)); return d;
}
__device__ __forceinline__ ull mul2(ull a, ull b) {
    ull d; asm("mul.rn.f32x2 %0, %1, %2;" : "=l"(d) : "l"(a), "l"(b)); return d;
}
__device__ __forceinline__ ull add2(ull a, ull b) {
    ull d; asm("add.rn.f32x2 %0, %1, %2;" : "=l"(d) : "l"(a), "l"(b)); return d;
}

// ---------------------------------------------------------------------------
// Fused kernel. Cooperative per-block precompute of the 3 folded circuit
// matrices; matrix stored duplicated-packed so one f32x2 FMA chain computes a
// row for TWO batch elements. 4 elems/thread, per-pair immediate float2 stores.
// out layout: [pi (B,3) | mu (B,3) | sigma (B,3)], row-major.
// ---------------------------------------------------------------------------
__global__ void __launch_bounds__(256, 3)
qmdn_fused(const float4* __restrict__ x4,
           const float* __restrict__ wp,
           const float* __restrict__ wm,
           const float* __restrict__ ws,
           float* __restrict__ out, int B) {
    __shared__ float sR[3][LAYERS][2][2][2][2];
    __shared__ float sP[3][LAYERS][4][4][2];
    __shared__ ull   sMre[3][16];                 // (Mre, Mre)
    __shared__ ull   sMim[3][16];                 // (Mim, Mim)

    int tid  = threadIdx.x;
    int wid  = tid >> 5;
    int lane = tid & 31;

    if (wid < 3) {
        int q = wid;
        const float* w = (q == 0) ? wp : (q == 1) ? wm : ws;

        if (lane < 16) {   // 16 Rot gates in parallel
            int l = lane >> 1, wi = lane & 1;
            float phi = w[(l * 2 + wi) * 3 + 0];
            float th  = w[(l * 2 + wi) * 3 + 1];
            float om  = w[(l * 2 + wi) * 3 + 2];
            float st, ct, sapo, capo, samo, camo;
            __sincosf(0.5f * th, &st, &ct);
            __sincosf(0.5f * (phi + om), &sapo, &capo);
            __sincosf(0.5f * (phi - om), &samo, &camo);
            sR[q][l][wi][0][0][0] =  capo * ct;  sR[q][l][wi][0][0][1] = -sapo * ct;
            sR[q][l][wi][0][1][0] = -camo * st;  sR[q][l][wi][0][1][1] = -samo * st;
            sR[q][l][wi][1][0][0] =  camo * st;  sR[q][l][wi][1][0][1] = -samo * st;
            sR[q][l][wi][1][1][0] =  capo * ct;  sR[q][l][wi][1][1][1] =  sapo * ct;
        }
        __syncwarp();

        if (lane < 16) {   // per-layer permuted Kronecker
            int r = lane >> 2, c = lane & 3;
            const int src[4] = {0, 2, 3, 1};
            int rs = src[r], i0 = rs >> 1, j0 = rs & 1, i1 = c >> 1, j1 = c & 1;
#pragma unroll
            for (int l = 0; l < LAYERS; l++) {
                float ar = sR[q][l][0][i0][i1][0], ai = sR[q][l][0][i0][i1][1];
                float br = sR[q][l][1][j0][j1][0], bi = sR[q][l][1][j0][j1][1];
                sP[q][l][r][c][0] = ar * br - ai * bi;
                sP[q][l][r][c][1] = ar * bi + ai * br;
            }
        }
        __syncwarp();

        for (int np = 4; np >= 1; np >>= 1) {   // log-tree product
            float res[4][2];
            if (lane < 16) {
                int r = lane >> 2, c = lane & 3;
                for (int m = 0; m < np; m++) {
                    float sr = 0.f, si = 0.f;
#pragma unroll
                    for (int k = 0; k < 4; k++) {
                        float ar = sP[q][2 * m + 1][r][k][0], ai = sP[q][2 * m + 1][r][k][1];
                        float br = sP[q][2 * m][k][c][0],     bi = sP[q][2 * m][k][c][1];
                        sr += ar * br - ai * bi;
                        si += ar * bi + ai * br;
                    }
                    res[m][0] = sr; res[m][1] = si;
                }
            }
            __syncwarp();
            if (lane < 16) {
                int r = lane >> 2, c = lane & 3;
                for (int m = 0; m < np; m++) {
                    sP[q][m][r][c][0] = res[m][0];
                    sP[q][m][r][c][1] = res[m][1];
                }
            }
            __syncwarp();
        }

        if (lane < 16) {   // fold column phases {1,-i,-i,-1}
            int r = lane >> 2, c = lane & 3;
            float ur = sP[q][0][r][c][0], ui = sP[q][0][r][c][1];
            float mr, mi;
            if (c == 0)      { mr =  ur; mi =  ui; }
            else if (c == 3) { mr = -ur; mi = -ui; }
            else             { mr =  ui; mi = -ur; }
            sMre[q][r * 4 + c] = pack2(mr, mr);
            sMim[q][r * 4 + c] = pack2(mi, mi);
        }
    }
    __syncthreads();

    // ------------------- main loop -------------------
    int nGroups = B >> 2;
    int stride  = gridDim.x * blockDim.x;
    const float CLIP_LO = EPS_F;
    const float CLIP_HI = 1.0f - EPS_F;
    const float LN2 = 0.69314718056f;
    size_t regionStride = 3 * (size_t)B;

    for (int t = blockIdx.x * blockDim.x + tid; t < nGroups; t += stride) {
        float4 xv = x4[t];

        // pair-packed amplitudes: pp[h][k] = (a[2h][k], a[2h+1][k])
        ull pp[2][4];
        {
            float s0a, c0a, s1a, c1a, s0b, c0b, s1b, c1b;
            __sincosf(0.5f * xv.x, &s0a, &c0a);
            __sincosf(0.78539816339744831f * xv.x, &s1a, &c1a);
            __sincosf(0.5f * xv.y, &s0b, &c0b);
            __sincosf(0.78539816339744831f * xv.y, &s1b, &c1b);
            pp[0][0] = pack2(c0a * c1a, c0b * c1b);
            pp[0][1] = pack2(c0a * s1a, c0b * s1b);
            pp[0][2] = pack2(s0a * c1a, s0b * c1b);
            pp[0][3] = pack2(s0a * s1a, s0b * s1b);
            __sincosf(0.5f * xv.z, &s0a, &c0a);
            __sincosf(0.78539816339744831f * xv.z, &s1a, &c1a);
            __sincosf(0.5f * xv.w, &s0b, &c0b);
            __sincosf(0.78539816339744831f * xv.w, &s1b, &c1b);
            pp[1][0] = pack2(c0a * c1a, c0b * c1b);
            pp[1][1] = pack2(c0a * s1a, c0b * s1b);
            pp[1][2] = pack2(s0a * c1a, s0b * c1b);
            pp[1][3] = pack2(s0a * s1a, s0b * s1b);
        }

#pragma unroll
        for (int q = 0; q < 3; q++) {
            // cache this circuit's matrix in regs (live only within this q)
            ull mre[16], mim[16];
#pragma unroll
            for (int i = 0; i < 16; i++) { mre[i] = sMre[q][i]; mim[i] = sMim[q][i]; }

            float* base = out + q * regionStride + (size_t)t * 12;
#pragma unroll
            for (int h = 0; h < 2; h++) {
                // rows for this pair: p2[j] = (p_e0, p_e1)
                float pa[4], pb[4];
                int nrows = (q == 0) ? 3 : 4;
#pragma unroll
                for (int j = 0; j < 4; j++) {
                    if (j >= nrows) break;
                    ull re2 = mul2(mre[j * 4 + 0], pp[h][0]);
                    re2 = fma2(mre[j * 4 + 1], pp[h][1], re2);
                    re2 = fma2(mre[j * 4 + 2], pp[h][2], re2);
                    re2 = fma2(mre[j * 4 + 3], pp[h][3], re2);
                    ull im2 = mul2(mim[j * 4 + 0], pp[h][0]);
                    im2 = fma2(mim[j * 4 + 1], pp[h][1], im2);
                    im2 = fma2(mim[j * 4 + 2], pp[h][2], im2);
                    im2 = fma2(mim[j * 4 + 3], pp[h][3], im2);
                    ull p2 = add2(mul2(re2, re2), mul2(im2, im2));
                    unpack2(p2, pa[j], pb[j]);
                }

                float o0, o1, o2, o3, o4, o5;
                if (q == 0) {
                    float ia = __fdividef(1.0f, pa[0] + pa[1] + pa[2]);
                    float ib = __fdividef(1.0f, pb[0] + pb[1] + pb[2]);
                    o0 = pa[0] * ia; o1 = pa[1] * ia; o2 = pa[2] * ia;
                    o3 = pb[0] * ib; o4 = pb[1] * ib; o5 = pb[2] * ib;
                } else {
#pragma unroll
                    for (int j = 0; j < 4; j++) {
                        pa[j] = fminf(fmaxf(pa[j], CLIP_LO), CLIP_HI);
                        pb[j] = fminf(fmaxf(pb[j], CLIP_LO), CLIP_HI);
                    }
                    if (q == 1) {
                        float la3 = __log2f(pa[3]), lb3 = __log2f(pb[3]);
                        o0 = (__log2f(pa[0]) - la3) * LN2;
                        o1 = (__log2f(pa[1]) - la3) * LN2;
                        o2 = (__log2f(pa[2]) - la3) * LN2;
                        o3 = (__log2f(pb[0]) - lb3) * LN2;
                        o4 = (__log2f(pb[1]) - lb3) * LN2;
                        o5 = (__log2f(pb[2]) - lb3) * LN2;
                    } else {
                        float ia = __fdividef(1.0f, pa[3]);
                        float ib = __fdividef(1.0f, pb[3]);
                        o0 = pa[0] * ia; o1 = pa[1] * ia; o2 = pa[2] * ia;
                        o3 = pb[0] * ib; o4 = pb[1] * ib; o5 = pb[2] * ib;
                    }
                }
                // 6 floats for this pair -> 3 aligned float2 stores
                float2* d2 = (float2*)(base + h * 6);
                d2[0] = make_float2(o0, o1);
                d2[1] = make_float2(o2, o3);
                d2[2] = make_float2(o4, o5);
            }
        }
    }
}

extern "C" void kernel_launch(void* const* d_in, const int* in_sizes, int n_in,
                              void* d_out, int out_size) {
    const float* x  = (const float*)d_in[0];
    const float* wp = (const float*)d_in[1];
    const float* wm = (const float*)d_in[2];
    const float* ws = (const float*)d_in[3];
    float* out = (float*)d_out;
    int B = in_sizes[0];

    int nGroups = B >> 2;
    int threads = 256;
    int blocks = (nGroups + threads - 1) / threads;   // 1024 @ B=2^20
    qmdn_fused<<<blocks, threads>>>((const float4*)x, wp, wm, ws, out, B);
}

// round 6
// speedup vs baseline: 1.1678x; 1.1209x over previous
#include <cuda_runtime.h>
#include <cstdint>

#define LAYERS 8
#define EPS_F 1e-7f

typedef unsigned long long ull;

__device__ __forceinline__ ull pack2(float x, float y) {
    ull r; asm("mov.b64 %0, {%1, %2};" : "=l"(r) : "f"(x), "f"(y)); return r;
}
__device__ __forceinline__ void unpack2(ull v, float& x, float& y) {
    asm("mov.b64 {%0, %1}, %2;" : "=f"(x), "=f"(y) : "l"(v));
}
__device__ __forceinline__ ull fma2(ull a, ull b, ull c) {
    ull d; asm("fma.rn.f32x2 %0, %1, %2, %3;" : "=l"(d) : "l"(a), "l"(b), "l"(c)); return d;
}
__device__ __forceinline__ ull mul2(ull a, ull b) {
    ull d; asm("mul.rn.f32x2 %0, %1, %2;" : "=l"(d) : "l"(a), "l"(b)); return d;
}
__device__ __forceinline__ ull add2(ull a, ull b) {
    ull d; asm("add.rn.f32x2 %0, %1, %2;" : "=l"(d) : "l"(a), "l"(b)); return d;
}

// ---------------------------------------------------------------------------
// Fused kernel. Per-block cooperative precompute of 3 folded circuit matrices
// stored duplicated-packed in smem: sMre[q][j][k]=(Mre,Mre), sMim likewise.
// Main loop: 4 elems/thread as two packed pairs; matrix rows are loaded from
// smem per row and dead immediately (no full-matrix register cache).
// out layout: [pi (B,3) | mu (B,3) | sigma (B,3)], row-major.
// ---------------------------------------------------------------------------
__global__ void __launch_bounds__(256)
qmdn_fused(const float4* __restrict__ x4,
           const float* __restrict__ wp,
           const float* __restrict__ wm,
           const float* __restrict__ ws,
           float* __restrict__ out, int B) {
    __shared__ float sR[3][LAYERS][2][2][2][2];
    __shared__ float sP[3][LAYERS][4][4][2];
    __shared__ ull   sMre[3][16];
    __shared__ ull   sMim[3][16];

    int tid  = threadIdx.x;
    int wid  = tid >> 5;
    int lane = tid & 31;

    if (wid < 3) {
        int q = wid;
        const float* w = (q == 0) ? wp : (q == 1) ? wm : ws;

        if (lane < 16) {   // 16 Rot gates in parallel
            int l = lane >> 1, wi = lane & 1;
            float phi = w[(l * 2 + wi) * 3 + 0];
            float th  = w[(l * 2 + wi) * 3 + 1];
            float om  = w[(l * 2 + wi) * 3 + 2];
            float st, ct, sapo, capo, samo, camo;
            __sincosf(0.5f * th, &st, &ct);
            __sincosf(0.5f * (phi + om), &sapo, &capo);
            __sincosf(0.5f * (phi - om), &samo, &camo);
            sR[q][l][wi][0][0][0] =  capo * ct;  sR[q][l][wi][0][0][1] = -sapo * ct;
            sR[q][l][wi][0][1][0] = -camo * st;  sR[q][l][wi][0][1][1] = -samo * st;
            sR[q][l][wi][1][0][0] =  camo * st;  sR[q][l][wi][1][0][1] = -samo * st;
            sR[q][l][wi][1][1][0] =  capo * ct;  sR[q][l][wi][1][1][1] =  sapo * ct;
        }
        __syncwarp();

        if (lane < 16) {   // per-layer permuted Kronecker
            int r = lane >> 2, c = lane & 3;
            const int src[4] = {0, 2, 3, 1};
            int rs = src[r], i0 = rs >> 1, j0 = rs & 1, i1 = c >> 1, j1 = c & 1;
#pragma unroll
            for (int l = 0; l < LAYERS; l++) {
                float ar = sR[q][l][0][i0][i1][0], ai = sR[q][l][0][i0][i1][1];
                float br = sR[q][l][1][j0][j1][0], bi = sR[q][l][1][j0][j1][1];
                sP[q][l][r][c][0] = ar * br - ai * bi;
                sP[q][l][r][c][1] = ar * bi + ai * br;
            }
        }
        __syncwarp();

        for (int np = 4; np >= 1; np >>= 1) {   // log-tree product
            float res[4][2];
            if (lane < 16) {
                int r = lane >> 2, c = lane & 3;
                for (int m = 0; m < np; m++) {
                    float sr = 0.f, si = 0.f;
#pragma unroll
                    for (int k = 0; k < 4; k++) {
                        float ar = sP[q][2 * m + 1][r][k][0], ai = sP[q][2 * m + 1][r][k][1];
                        float br = sP[q][2 * m][k][c][0],     bi = sP[q][2 * m][k][c][1];
                        sr += ar * br - ai * bi;
                        si += ar * bi + ai * br;
                    }
                    res[m][0] = sr; res[m][1] = si;
                }
            }
            __syncwarp();
            if (lane < 16) {
                int r = lane >> 2, c = lane & 3;
                for (int m = 0; m < np; m++) {
                    sP[q][m][r][c][0] = res[m][0];
                    sP[q][m][r][c][1] = res[m][1];
                }
            }
            __syncwarp();
        }

        if (lane < 16) {   // fold column phases {1,-i,-i,-1}
            int r = lane >> 2, c = lane & 3;
            float ur = sP[q][0][r][c][0], ui = sP[q][0][r][c][1];
            float mr, mi;
            if (c == 0)      { mr =  ur; mi =  ui; }
            else if (c == 3) { mr = -ur; mi = -ui; }
            else             { mr =  ui; mi = -ur; }
            sMre[q][r * 4 + c] = pack2(mr, mr);
            sMim[q][r * 4 + c] = pack2(mi, mi);
        }
    }
    __syncthreads();

    // ------------------- main loop -------------------
    int nGroups = B >> 2;
    int stride  = gridDim.x * blockDim.x;
    const float CLIP_LO = EPS_F;
    const float CLIP_HI = 1.0f - EPS_F;
    const float LN2 = 0.69314718056f;
    size_t regionStride = 3 * (size_t)B;

    for (int t = blockIdx.x * blockDim.x + tid; t < nGroups; t += stride) {
        float4 xv = x4[t];

        // pair-packed amplitudes: pp[h][k] = (a[2h][k], a[2h+1][k])
        ull pp[2][4];
        {
            float s0a, c0a, s1a, c1a, s0b, c0b, s1b, c1b;
            __sincosf(0.5f * xv.x, &s0a, &c0a);
            __sincosf(0.78539816339744831f * xv.x, &s1a, &c1a);
            __sincosf(0.5f * xv.y, &s0b, &c0b);
            __sincosf(0.78539816339744831f * xv.y, &s1b, &c1b);
            pp[0][0] = pack2(c0a * c1a, c0b * c1b);
            pp[0][1] = pack2(c0a * s1a, c0b * s1b);
            pp[0][2] = pack2(s0a * c1a, s0b * c1b);
            pp[0][3] = pack2(s0a * s1a, s0b * s1b);
            __sincosf(0.5f * xv.z, &s0a, &c0a);
            __sincosf(0.78539816339744831f * xv.z, &s1a, &c1a);
            __sincosf(0.5f * xv.w, &s0b, &c0b);
            __sincosf(0.78539816339744831f * xv.w, &s1b, &c1b);
            pp[1][0] = pack2(c0a * c1a, c0b * c1b);
            pp[1][1] = pack2(c0a * s1a, c0b * s1b);
            pp[1][2] = pack2(s0a * c1a, s0b * c1b);
            pp[1][3] = pack2(s0a * s1a, s0b * s1b);
        }

#pragma unroll
        for (int q = 0; q < 3; q++) {
            int nrows = (q == 0) ? 3 : 4;
            ull ph[2][4];    // packed probs [pair][row]
#pragma unroll
            for (int j = 0; j < 4; j++) {
                if (j >= nrows) break;
                // row loads: live only inside this j iteration
                ull mr0 = sMre[q][j * 4 + 0], mr1 = sMre[q][j * 4 + 1];
                ull mr2 = sMre[q][j * 4 + 2], mr3 = sMre[q][j * 4 + 3];
                ull mi0 = sMim[q][j * 4 + 0], mi1 = sMim[q][j * 4 + 1];
                ull mi2 = sMim[q][j * 4 + 2], mi3 = sMim[q][j * 4 + 3];
#pragma unroll
                for (int h = 0; h < 2; h++) {
                    ull re2 = mul2(mr0, pp[h][0]);
                    re2 = fma2(mr1, pp[h][1], re2);
                    re2 = fma2(mr2, pp[h][2], re2);
                    re2 = fma2(mr3, pp[h][3], re2);
                    ull im2 = mul2(mi0, pp[h][0]);
                    im2 = fma2(mi1, pp[h][1], im2);
                    im2 = fma2(mi2, pp[h][2], im2);
                    im2 = fma2(mi3, pp[h][3], im2);
                    ph[h][j] = add2(mul2(re2, re2), mul2(im2, im2));
                }
            }

            float* base = out + q * regionStride + (size_t)t * 12;
#pragma unroll
            for (int h = 0; h < 2; h++) {
                float pa[4], pb[4];
#pragma unroll
                for (int j = 0; j < 4; j++) {
                    if (j >= nrows) break;
                    unpack2(ph[h][j], pa[j], pb[j]);
                }
                float o0, o1, o2, o3, o4, o5;
                if (q == 0) {
                    float ia = __fdividef(1.0f, pa[0] + pa[1] + pa[2]);
                    float ib = __fdividef(1.0f, pb[0] + pb[1] + pb[2]);
                    o0 = pa[0] * ia; o1 = pa[1] * ia; o2 = pa[2] * ia;
                    o3 = pb[0] * ib; o4 = pb[1] * ib; o5 = pb[2] * ib;
                } else {
#pragma unroll
                    for (int j = 0; j < 4; j++) {
                        pa[j] = fminf(fmaxf(pa[j], CLIP_LO), CLIP_HI);
                        pb[j] = fminf(fmaxf(pb[j], CLIP_LO), CLIP_HI);
                    }
                    if (q == 1) {
                        float la3 = __log2f(pa[3]), lb3 = __log2f(pb[3]);
                        o0 = (__log2f(pa[0]) - la3) * LN2;
                        o1 = (__log2f(pa[1]) - la3) * LN2;
                        o2 = (__log2f(pa[2]) - la3) * LN2;
                        o3 = (__log2f(pb[0]) - lb3) * LN2;
                        o4 = (__log2f(pb[1]) - lb3) * LN2;
                        o5 = (__log2f(pb[2]) - lb3) * LN2;
                    } else {
                        float ia = __fdividef(1.0f, pa[3]);
                        float ib = __fdividef(1.0f, pb[3]);
                        o0 = pa[0] * ia; o1 = pa[1] * ia; o2 = pa[2] * ia;
                        o3 = pb[0] * ib; o4 = pb[1] * ib; o5 = pb[2] * ib;
                    }
                }
                float2* d2 = (float2*)(base + h * 6);
                d2[0] = make_float2(o0, o1);
                d2[1] = make_float2(o2, o3);
                d2[2] = make_float2(o4, o5);
            }
        }
    }
}

extern "C" void kernel_launch(void* const* d_in, const int* in_sizes, int n_in,
                              void* d_out, int out_size) {
    const float* x  = (const float*)d_in[0];
    const float* wp = (const float*)d_in[1];
    const float* wm = (const float*)d_in[2];
    const float* ws = (const float*)d_in[3];
    float* out = (float*)d_out;
    int B = in_sizes[0];

    int nGroups = B >> 2;
    int threads = 256;
    int blocks = (nGroups + threads - 1) / threads;   // 1024 @ B=2^20
    qmdn_fused<<<blocks, threads>>>((const float4*)x, wp, wm, ws, out, B);
}

// round 7
// speedup vs baseline: 2.3906x; 2.0471x over previous
#include <cuda_runtime.h>
#include <cstdint>

#define LAYERS 8
#define EPS_F 1e-7f

// ---------------------------------------------------------------------------
// Fused kernel, quadratic-form version.
// Prologue (warps 0-2, one per circuit): build folded 4x4 complex matrix M',
// then per output row j the 3x3 real matrix C^j such that
//     p_j = (1,u0,v0) C^j (1,u1,v1)^T,  u0=cos x, v0=sin x,
//                                       u1=cos(pi x/2), v1=sin(pi x/2).
// Main loop: 4 elems/thread, 8 FMA per row, no complex arithmetic, no squares.
// out layout: [pi (B,3) | mu (B,3) | sigma (B,3)], row-major.
// ---------------------------------------------------------------------------
__global__ void __launch_bounds__(256, 4)
qmdn_fused(const float4* __restrict__ x4,
           const float* __restrict__ wp,
           const float* __restrict__ wm,
           const float* __restrict__ ws,
           float* __restrict__ out, int B) {
    __shared__ float sR[3][LAYERS][2][2][2][2];
    __shared__ float sP[3][LAYERS][4][4][2];
    __shared__ float sM[3][4][4][2];      // folded matrices (row, col, re/im)
    __shared__ float sC[3][4][9];         // 3x3 quadratic-form per (circuit,row)

    int tid  = threadIdx.x;
    int wid  = tid >> 5;
    int lane = tid & 31;

    if (wid < 3) {
        int q = wid;
        const float* w = (q == 0) ? wp : (q == 1) ? wm : ws;

        if (lane < 16) {   // 16 Rot gates in parallel
            int l = lane >> 1, wi = lane & 1;
            float phi = w[(l * 2 + wi) * 3 + 0];
            float th  = w[(l * 2 + wi) * 3 + 1];
            float om  = w[(l * 2 + wi) * 3 + 2];
            float st, ct, sapo, capo, samo, camo;
            __sincosf(0.5f * th, &st, &ct);
            __sincosf(0.5f * (phi + om), &sapo, &capo);
            __sincosf(0.5f * (phi - om), &samo, &camo);
            sR[q][l][wi][0][0][0] =  capo * ct;  sR[q][l][wi][0][0][1] = -sapo * ct;
            sR[q][l][wi][0][1][0] = -camo * st;  sR[q][l][wi][0][1][1] = -samo * st;
            sR[q][l][wi][1][0][0] =  camo * st;  sR[q][l][wi][1][0][1] = -samo * st;
            sR[q][l][wi][1][1][0] =  capo * ct;  sR[q][l][wi][1][1][1] =  sapo * ct;
        }
        __syncwarp();

        if (lane < 16) {   // per-layer permuted Kronecker
            int r = lane >> 2, c = lane & 3;
            const int src[4] = {0, 2, 3, 1};
            int rs = src[r], i0 = rs >> 1, j0 = rs & 1, i1 = c >> 1, j1 = c & 1;
#pragma unroll
            for (int l = 0; l < LAYERS; l++) {
                float ar = sR[q][l][0][i0][i1][0], ai = sR[q][l][0][i0][i1][1];
                float br = sR[q][l][1][j0][j1][0], bi = sR[q][l][1][j0][j1][1];
                sP[q][l][r][c][0] = ar * br - ai * bi;
                sP[q][l][r][c][1] = ar * bi + ai * br;
            }
        }
        __syncwarp();

        for (int np = 4; np >= 1; np >>= 1) {   // log-tree product
            float res[4][2];
            if (lane < 16) {
                int r = lane >> 2, c = lane & 3;
                for (int m = 0; m < np; m++) {
                    float sr = 0.f, si = 0.f;
#pragma unroll
                    for (int k = 0; k < 4; k++) {
                        float ar = sP[q][2 * m + 1][r][k][0], ai = sP[q][2 * m + 1][r][k][1];
                        float br = sP[q][2 * m][k][c][0],     bi = sP[q][2 * m][k][c][1];
                        sr += ar * br - ai * bi;
                        si += ar * bi + ai * br;
                    }
                    res[m][0] = sr; res[m][1] = si;
                }
            }
            __syncwarp();
            if (lane < 16) {
                int r = lane >> 2, c = lane & 3;
                for (int m = 0; m < np; m++) {
                    sP[q][m][r][c][0] = res[m][0];
                    sP[q][m][r][c][1] = res[m][1];
                }
            }
            __syncwarp();
        }

        if (lane < 16) {   // fold column phases {1,-i,-i,-1}
            int r = lane >> 2, c = lane & 3;
            float ur = sP[q][0][r][c][0], ui = sP[q][0][r][c][1];
            float mr, mi;
            if (c == 0)      { mr =  ur; mi =  ui; }
            else if (c == 3) { mr = -ur; mi = -ui; }
            else             { mr =  ui; mi = -ur; }
            sM[q][r][c][0] = mr;
            sM[q][r][c][1] = mi;
        }
        __syncwarp();

        // build C^j: lane j < 4 handles row j
        if (lane < 4) {
            int j = lane;
            float mr[4], mi[4];
#pragma unroll
            for (int k = 0; k < 4; k++) { mr[k] = sM[q][j][k][0]; mi[k] = sM[q][j][k][1]; }
            // basis vectors: prod index 0:cc, 1:cs(+sc), 2:ss  ->  coeffs of (1,u,v)
            const float bas[3][3] = { {0.5f,  0.5f, 0.f},
                                      {0.f,   0.f,  0.5f},
                                      {0.5f, -0.5f, 0.f} };
            float C[9] = {0,0,0,0,0,0,0,0,0};
#pragma unroll
            for (int k = 0; k < 4; k++)
#pragma unroll
                for (int l = 0; l < 4; l++) {
                    float Q = mr[k] * mr[l] + mi[k] * mi[l];   // Re(z_k conj(z_l))
                    int a0 = (k >> 1) + (l >> 1);   // 0,1,2 -> cc, cs, ss (qubit0)
                    int b1 = (k & 1) + (l & 1);     // qubit1
#pragma unroll
                    for (int al = 0; al < 3; al++)
#pragma unroll
                        for (int be = 0; be < 3; be++)
                            C[al * 3 + be] += Q * bas[a0][al] * bas[b1][be];
                }
#pragma unroll
            for (int i = 0; i < 9; i++) sC[q][j][i] = C[i];
        }
    }
    __syncthreads();

    // ------------------- main loop: 4 elems/thread -------------------
    int nGroups = B >> 2;
    int stride  = gridDim.x * blockDim.x;
    const float CLIP_LO = EPS_F;
    const float CLIP_HI = 1.0f - EPS_F;
    const float LN2 = 0.69314718056f;
    size_t regionStride = 3 * (size_t)B;

    for (int t = blockIdx.x * blockDim.x + tid; t < nGroups; t += stride) {
        float4 xv = x4[t];
        float xs[4] = {xv.x, xv.y, xv.z, xv.w};

        float u0[4], v0[4], u1[4], v1[4];
#pragma unroll
        for (int e = 0; e < 4; e++) {
            __sincosf(xs[e], &v0[e], &u0[e]);
            __sincosf(1.5707963267948966f * xs[e], &v1[e], &u1[e]);
        }

#pragma unroll
        for (int q = 0; q < 3; q++) {
            int nrows = (q == 0) ? 3 : 4;
            float o[12];
#pragma unroll
            for (int e = 0; e < 4; e++) {
                float p[4];
#pragma unroll
                for (int j = 0; j < 4; j++) {
                    if (j >= nrows) break;
                    const float* C = sC[q][j];
                    float w0 = fmaf(v1[e], C[2], fmaf(u1[e], C[1], C[0]));
                    float w1 = fmaf(v1[e], C[5], fmaf(u1[e], C[4], C[3]));
                    float w2 = fmaf(v1[e], C[8], fmaf(u1[e], C[7], C[6]));
                    p[j] = fmaf(v0[e], w2, fmaf(u0[e], w1, w0));
                }
                if (q == 0) {
                    float inv = __fdividef(1.0f, p[0] + p[1] + p[2]);
                    o[e * 3 + 0] = p[0] * inv;
                    o[e * 3 + 1] = p[1] * inv;
                    o[e * 3 + 2] = p[2] * inv;
                } else {
                    float pc[4];
#pragma unroll
                    for (int j = 0; j < 4; j++)
                        pc[j] = fminf(fmaxf(p[j], CLIP_LO), CLIP_HI);
                    if (q == 1) {
                        float l3 = __log2f(pc[3]);
                        o[e * 3 + 0] = (__log2f(pc[0]) - l3) * LN2;
                        o[e * 3 + 1] = (__log2f(pc[1]) - l3) * LN2;
                        o[e * 3 + 2] = (__log2f(pc[2]) - l3) * LN2;
                    } else {
                        float inv = __fdividef(1.0f, pc[3]);
                        o[e * 3 + 0] = pc[0] * inv;
                        o[e * 3 + 1] = pc[1] * inv;
                        o[e * 3 + 2] = pc[2] * inv;
                    }
                }
            }
            float4* dst = (float4*)(out + q * regionStride + (size_t)t * 12);
            dst[0] = make_float4(o[0], o[1], o[2],  o[3]);
            dst[1] = make_float4(o[4], o[5], o[6],  o[7]);
            dst[2] = make_float4(o[8], o[9], o[10], o[11]);
        }
    }
}

extern "C" void kernel_launch(void* const* d_in, const int* in_sizes, int n_in,
                              void* d_out, int out_size) {
    const float* x  = (const float*)d_in[0];
    const float* wp = (const float*)d_in[1];
    const float* wm = (const float*)d_in[2];
    const float* ws = (const float*)d_in[3];
    float* out = (float*)d_out;
    int B = in_sizes[0];

    int nGroups = B >> 2;
    int threads = 256;
    int blocks = (nGroups + threads - 1) / threads;   // 1024 @ B=2^20
    qmdn_fused<<<blocks, threads>>>((const float4*)x, wp, wm, ws, out, B);
}